// round 3
// baseline (speedup 1.0000x reference)
#include <cuda_runtime.h>
#include <cuda_bf16.h>
#include <cooperative_groups.h>
#include <math.h>

namespace cg = cooperative_groups;

// HopAttentionLayer: B=256, T=64, N=2048, D=128
// attention[b,n] = softmax_n( 64 * <context[b,n,:], W[128:256]> )   (shift
// invariance kills tgt_term and bias). out = attention[:, :, None] * context.
//
// Cluster-of-8 per batch. Each CTA owns 256 rows (128 KB) cached in SMEM
// during the dot pass; split-softmax partials combined across the cluster via
// DSMEM; scale pass reads SMEM, not DRAM. Context is read from HBM once.

#define BB    256
#define NN    2048
#define DD    128
#define TPB   1024
#define CLSZ  8
#define ROWS  (NN / CLSZ)          // 256 rows per CTA
#define RPW   (ROWS / 32)          // 8 rows per warp

// smem layout (floats): tile[ROWS*DD] | scores[ROWS] | red[8] | part[2] | stat[2]
#define SM_FLOATS (ROWS * DD + ROWS + 8 + 2 + 2)
#define SM_BYTES  (SM_FLOATS * 4)

__global__ __launch_bounds__(TPB, 1) __cluster_dims__(CLSZ, 1, 1)
void hop_attention_cluster(const float* __restrict__ ctx,
                           const float* __restrict__ W,
                           float* __restrict__ out)
{
    extern __shared__ float sm[];
    float* tile   = sm;                    // ROWS*DD
    float* scores = tile + ROWS * DD;      // ROWS
    float* red    = scores + ROWS;         // 8
    float* part   = red + 8;               // [0]=m_loc, [1]=sum_loc
    float* stat   = part + 2;              // [0]=g_max, [1]=1/g_sum

    const int b    = blockIdx.x >> 3;
    const int rank = blockIdx.x & 7;
    const int tid  = threadIdx.x;
    const int lane = tid & 31;
    const int warp = tid >> 5;

    const float* __restrict__ cb = ctx + ((size_t)b * NN + (size_t)rank * ROWS) * DD;
    float* __restrict__ ob       = out + ((size_t)b * NN + (size_t)rank * ROWS) * DD;

    cg::cluster_group cluster = cg::this_cluster();

    // Wc = W[128..255]; lane owns 4 contiguous components.
    const float4 wc = reinterpret_cast<const float4*>(W + DD)[lane];

    // ---------- Phase A: load tile to SMEM + compute scores ----------
    // warp w handles rows [w*RPW, w*RPW+RPW). Batch loads first for MLP.
    {
        float4 c[RPW];
        const int row0 = warp * RPW;
        #pragma unroll
        for (int r = 0; r < RPW; r++)
            c[r] = reinterpret_cast<const float4*>(cb + (row0 + r) * DD)[lane];
        #pragma unroll
        for (int r = 0; r < RPW; r++) {
            reinterpret_cast<float4*>(tile + (row0 + r) * DD)[lane] = c[r];
            float d = fmaf(c[r].x, wc.x, fmaf(c[r].y, wc.y,
                      fmaf(c[r].z, wc.z, c[r].w * wc.w)));
            #pragma unroll
            for (int o = 16; o > 0; o >>= 1)
                d += __shfl_xor_sync(0xffffffffu, d, o);
            if (lane == 0) scores[row0 + r] = d * 64.0f;   // T = 64
        }
    }
    __syncthreads();

    // ---------- Local max over 256 scores (warps 0..7, one elem/thread) ----------
    float m = -INFINITY;
    if (tid < ROWS) m = scores[tid];
    #pragma unroll
    for (int o = 16; o > 0; o >>= 1)
        m = fmaxf(m, __shfl_xor_sync(0xffffffffu, m, o));
    if (tid < ROWS && lane == 0) red[warp] = m;
    __syncthreads();
    if (tid == 0) {
        float mm = red[0];
        #pragma unroll
        for (int i = 1; i < 8; i++) mm = fmaxf(mm, red[i]);
        part[0] = mm;
    }
    __syncthreads();
    const float m_loc = part[0];

    // ---------- Local sum of exp(score - m_loc) ----------
    float e = 0.0f;
    if (tid < ROWS) e = __expf(scores[tid] - m_loc);
    #pragma unroll
    for (int o = 16; o > 0; o >>= 1)
        e += __shfl_xor_sync(0xffffffffu, e, o);
    if (tid < ROWS && lane == 0) red[warp] = e;
    __syncthreads();
    if (tid == 0) {
        float ss = 0.0f;
        #pragma unroll
        for (int i = 0; i < 8; i++) ss += red[i];
        part[1] = ss;
    }
    __syncthreads();

    // ---------- Cluster combine: global max + rescaled sum ----------
    cluster.sync();   // release my (part[0],part[1]) to peers; acquire theirs

    if (warp == 0) {
        float pm = -INFINITY, ps = 0.0f;
        if (lane < CLSZ) {
            const float* rp = (const float*)cluster.map_shared_rank(part, lane);
            pm = rp[0];
            ps = rp[1];
        }
        // gm = max over 8 lanes
        float gm = pm;
        #pragma unroll
        for (int o = 4; o > 0; o >>= 1)
            gm = fmaxf(gm, __shfl_xor_sync(0x000000ffu, gm, o));
        float contrib = (lane < CLSZ) ? ps * __expf(pm - gm) : 0.0f;
        #pragma unroll
        for (int o = 4; o > 0; o >>= 1)
            contrib += __shfl_xor_sync(0x000000ffu, contrib, o);
        if (lane == 0) {
            stat[0] = gm;
            stat[1] = 1.0f / contrib;
        }
    }
    __syncthreads();
    cluster.sync();   // no CTA exits / overwrites part[] while peers still reading

    // ---------- attn per local row ----------
    if (tid < ROWS)
        scores[tid] = __expf(scores[tid] - stat[0]) * stat[1];
    __syncthreads();

    // ---------- Phase B: out = attn[row] * tile (SMEM -> GMEM) ----------
    {
        const float4* __restrict__ t4 = reinterpret_cast<const float4*>(tile);
        float4* __restrict__ o4 = reinterpret_cast<float4*>(ob);
        #pragma unroll
        for (int k = 0; k < (ROWS * DD / 4) / TPB; k++) {   // 8 iters
            const int i = tid + k * TPB;
            const float a = scores[i >> 5];                  // 32 float4 per row
            float4 c = t4[i];
            c.x *= a; c.y *= a; c.z *= a; c.w *= a;
            o4[i] = c;
        }
    }
}

extern "C" void kernel_launch(void* const* d_in, const int* in_sizes, int n_in,
                              void* d_out, int out_size)
{
    // metadata order: targetsentence_emb, context_emb, W, b
    // targetsentence_emb and b are mathematically irrelevant (softmax shift
    // invariance) — never read.
    const float* ctx = (const float*)d_in[1];
    const float* W   = (const float*)d_in[2];
    float* out = (float*)d_out;

    // Idempotent, not a stream op (legal under graph capture); called
    // unconditionally to honor the no-static-guards rule.
    cudaFuncSetAttribute(hop_attention_cluster,
                         cudaFuncAttributeMaxDynamicSharedMemorySize,
                         SM_BYTES);

    hop_attention_cluster<<<BB * CLSZ, TPB, SM_BYTES>>>(ctx, W, out);
}

// round 4
// speedup vs baseline: 1.0372x; 1.0372x over previous
#include <cuda_runtime.h>
#include <cuda_bf16.h>
#include <math.h>

// HopAttentionLayer: B=256, T=64, N=2048, D=128
// attention[b,n] = softmax_n( 64 * <context[b,n,:], W[128:256]> )  (softmax
// shift invariance kills tgt_term and bias). out = attention[:,:,None]*ctx.
//
// R4: L2-resident reuse. 128 CTAs x 1024 thr, 2 batches per CTA (256=128*2).
// Live ctx working set = 128 MB ~ L2 capacity. Phase A: stream 1 MB slice,
// scores in smem. Block softmax. Phase B: re-read in REVERSE order (most
// recent first, LRU-friendly) with __ldcs, write with __stcs (streaming,
// don't evict resident ctx). No clusters, no big smem, no sync dead time.

#define BB   256
#define NN   2048
#define DD   128
#define TPB  1024
#define GRID 128
#define BPC  (BB / GRID)           // 2 batches per CTA
#define NWARP (TPB / 32)

__global__ __launch_bounds__(TPB, 1)
void hop_attention_l2(const float* __restrict__ ctx,
                      const float* __restrict__ W,
                      float* __restrict__ out)
{
    __shared__ float s[NN];        // scores -> attn weights
    __shared__ float red[NWARP];
    __shared__ float stat[2];      // [0]=max, [1]=inv_sum

    const int tid  = threadIdx.x;
    const int lane = tid & 31;
    const int warp = tid >> 5;

    // Wc = W[128..255]; lane owns 4 contiguous components.
    const float4 wc = reinterpret_cast<const float4*>(W + DD)[lane];

    for (int bi = 0; bi < BPC; bi++) {
        const int b = blockIdx.x + bi * GRID;
        const float* __restrict__ cb = ctx + (size_t)b * NN * DD;
        float* __restrict__ ob       = out + (size_t)b * NN * DD;

        // ---------- Phase A: scores[n] = 64 * <ctx[n,:], Wc> ----------
        // Warp-per-row, strided; unroll for MLP. Plain loads (want L2 resident).
        #pragma unroll 8
        for (int n = warp; n < NN; n += NWARP) {
            const float4 c = reinterpret_cast<const float4*>(cb + n * DD)[lane];
            float d = fmaf(c.x, wc.x, fmaf(c.y, wc.y, fmaf(c.z, wc.z, c.w * wc.w)));
            #pragma unroll
            for (int o = 16; o > 0; o >>= 1)
                d += __shfl_xor_sync(0xffffffffu, d, o);
            if (lane == 0) s[n] = d * 64.0f;   // T = 64
        }
        __syncthreads();

        // ---------- Block softmax over 2048 scores ----------
        float m = fmaxf(s[tid], s[tid + TPB]);
        #pragma unroll
        for (int o = 16; o > 0; o >>= 1)
            m = fmaxf(m, __shfl_xor_sync(0xffffffffu, m, o));
        if (lane == 0) red[warp] = m;
        __syncthreads();
        if (warp == 0) {
            m = red[lane];
            #pragma unroll
            for (int o = 16; o > 0; o >>= 1)
                m = fmaxf(m, __shfl_xor_sync(0xffffffffu, m, o));
            if (lane == 0) stat[0] = m;
        }
        __syncthreads();
        m = stat[0];

        float e0 = __expf(s[tid] - m);
        float e1 = __expf(s[tid + TPB] - m);
        s[tid]       = e0;
        s[tid + TPB] = e1;
        float sum = e0 + e1;
        #pragma unroll
        for (int o = 16; o > 0; o >>= 1)
            sum += __shfl_xor_sync(0xffffffffu, sum, o);
        if (lane == 0) red[warp] = sum;
        __syncthreads();
        if (warp == 0) {
            sum = red[lane];
            #pragma unroll
            for (int o = 16; o > 0; o >>= 1)
                sum += __shfl_xor_sync(0xffffffffu, sum, o);
            if (lane == 0) stat[1] = 1.0f / sum;
        }
        __syncthreads();
        const float inv = stat[1];

        // ---------- Phase B: out = attn[n] * ctx, REVERSE order ----------
        // Most-recently-loaded rows re-read first => L2/L1 hits. __ldcs marks
        // lines evict-first after this read; __stcs keeps writes from
        // displacing other CTAs' resident ctx.
        const float4* __restrict__ cb4 = reinterpret_cast<const float4*>(cb);
        float4* __restrict__ ob4 = reinterpret_cast<float4*>(ob);
        const int total4 = NN * DD / 4;   // 65536 float4, 32 per row
        #pragma unroll 4
        for (int k = 0; k < total4 / TPB; k++) {   // 64 iters
            const int i = (total4 - TPB) - k * TPB + tid;   // descending blocks
            const float a = s[i >> 5] * inv;
            float4 c = __ldcs(cb4 + i);
            c.x *= a; c.y *= a; c.z *= a; c.w *= a;
            __stcs(ob4 + i, c);
        }
        __syncthreads();   // protect s[] before next batch's phase A writes
    }
}

extern "C" void kernel_launch(void* const* d_in, const int* in_sizes, int n_in,
                              void* d_out, int out_size)
{
    // metadata order: targetsentence_emb, context_emb, W, b
    // targetsentence_emb and b are mathematically irrelevant (softmax shift
    // invariance) — never read.
    const float* ctx = (const float*)d_in[1];
    const float* W   = (const float*)d_in[2];
    float* out = (float*)d_out;

    hop_attention_l2<<<GRID, TPB>>>(ctx, W, out);
}